// round 15
// baseline (speedup 1.0000x reference)
#include <cuda_runtime.h>

// OrbitalSpectralConv: B=8, C=128, H=W=128; kept modes: 32 kx rows x 17 ky cols.
// kx rows: mk 0..16 -> kx = mk; mk 17..31 -> kx = mk+96 == -(32-mk) mod 128.
#define NKY   17
#define NMODE 544           // 32*17
#define NSLICE 1024         // B*C

// Scratch (allocation banned -> device globals).
__device__ float2 g_Xf[128 * NMODE * 8];         // 4.45 MB  [ct][m][b]
__device__ float2 g_Y [NSLICE * NMODE];          // 4.45 MB  [b][c][m]  (ct 0..63)
__device__ float2 g_Y2[NSLICE * NMODE];          // 4.45 MB  [b][c][m]  (ct 64..127)

// ===========================================================================
// Fused forward per (b,c) slice. 320 threads, 56832 B dynamic smem,
// forced 4 blocks/SM (occupancy was the binding constraint at regs=54).
// Phase A (w-DFT, DOUBLE-folded, 256 threads = 64 h x 4 ky-groups):
//   even ky=2j: re = Sp0+Sp64+(-1)^j Sp32 + sum_{w=1..31} Ae[w] cos; im = -sum Be sin
//   odd  ky=2j+1: re = Sp0-Sp64 + sum Ao cos; im = -(-1)^j Sm32 - sum Bo sin
//   QE[h][w]=(Ae,Be), QO[h][w]=(Ao,Bo); Ae/Ao = Sp[w]+/-Sp[64-w];
//   Be/Bo = Sm[w]-/+Sm[64-w]; Sp[w]=x[w]+x[128-w], Sm[w]=x[w]-x[128-w].
// Phase B (h-DFT, folded, rotation trig, 289 threads = (a,ky)):
//   Xf[+a]=(C1+S2, C2-S1), Xf[-a]=(C1-S2, C2+S1), scaled 1/16384 -> g_Xf[c][m][b]
// ===========================================================================
__global__ __launch_bounds__(320, 4) void k_fwd(const float* __restrict__ X) {
    extern __shared__ char smraw[];
    float4* Bd = (float4*)smraw;                 // [64]   (Sp0, Sp64, Sp32, Sm32)
    float2* Te = (float2*)(Bd + 64);             // [32][10] cos/sin(2pi*2j*w/128)
    float2* To = Te + 32 * 10;                   // [32][8]  cos/sin(2pi*(2j+1)*w/128)
    float2* Gs = To + 32 * 8;                    // [128][17]
    float2* QE = Gs + 128 * NKY;                 // [64][33]  (Ae, Be)
    float2* QO = QE + 64 * 33;                   // [64][33]  (Ao, Bo)

    const int tid = threadIdx.x;

    if (tid < 320) {
        int w = tid / 10, j = tid - (tid / 10) * 10;
        float s, c;
        sincospif((float)((w * 2 * j) & 127) * (2.0f / 128.0f), &s, &c);
        Te[tid] = make_float2(c, s);
    }
    if (tid < 256) {
        int w = tid >> 3, j = tid & 7;
        float s, c;
        sincospif((float)((w * (2 * j + 1)) & 127) * (2.0f / 128.0f), &s, &c);
        To[tid] = make_float2(c, s);
    }

    const float* Xp = X + (size_t)blockIdx.x * 16384;

    const int hl  = tid & 63;
    const int grp = tid >> 6;

    for (int half = 0; half < 2; half++) {
        __syncthreads();    // covers trig init (1st) and QE/QO/Bd reuse (2nd)
        for (int i = tid; i < 2048; i += 320) {
            int hr = i >> 5, w = i & 31;
            const float* row = Xp + (half * 64 + hr) * 128;
            if (w == 0) {
                float x0 = row[0], x64 = row[64], x32 = row[32], x96 = row[96];
                Bd[hr] = make_float4(x0, x64, x32 + x96, x32 - x96);
            } else {
                float xa = row[w], xb = row[64 - w], xc = row[64 + w], xd = row[128 - w];
                float sp  = xa + xd, sm  = xa - xd;
                float spb = xb + xc, smb = xb - xc;
                QE[hr * 33 + w] = make_float2(sp + spb, sm - smb);
                QO[hr * 33 + w] = make_float2(sp - spb, sm + smb);
            }
        }
        __syncthreads();

        if (grp < 4) {
            const float4 bd = Bd[hl];
            const int h = half * 64 + hl;
            const float2* Qr = (grp < 2 ? QE : QO) + hl * 33;

            if (grp == 0) {                       // even ky 0,2,4,6,8
                float gr[5], gi[5];
                #pragma unroll
                for (int j = 0; j < 5; j++) {
                    gr[j] = bd.x + bd.y + ((j & 1) ? -bd.z : bd.z);
                    gi[j] = 0.f;
                }
                #pragma unroll 4
                for (int w = 1; w < 32; w++) {
                    float2 q = Qr[w];
                    float a  = q.x;
                    float nb = -q.y;
                    float4 t01 = *(const float4*)(Te + w * 10);
                    float4 t23 = *(const float4*)(Te + w * 10 + 2);
                    float2 t4  = Te[w * 10 + 4];
                    gr[0]=fmaf(t01.x,a,gr[0]); gi[0]=fmaf(t01.y,nb,gi[0]);
                    gr[1]=fmaf(t01.z,a,gr[1]); gi[1]=fmaf(t01.w,nb,gi[1]);
                    gr[2]=fmaf(t23.x,a,gr[2]); gi[2]=fmaf(t23.y,nb,gi[2]);
                    gr[3]=fmaf(t23.z,a,gr[3]); gi[3]=fmaf(t23.w,nb,gi[3]);
                    gr[4]=fmaf(t4.x ,a,gr[4]); gi[4]=fmaf(t4.y ,nb,gi[4]);
                }
                #pragma unroll
                for (int j = 0; j < 5; j++)
                    Gs[h * NKY + 2 * j] = make_float2(gr[j], gi[j]);
            } else if (grp == 1) {                // even ky 10,12,14,16 (j=5..8)
                float gr[4], gi[4];
                #pragma unroll
                for (int j = 0; j < 4; j++) {
                    int jj = 5 + j;
                    gr[j] = bd.x + bd.y + ((jj & 1) ? -bd.z : bd.z);
                    gi[j] = 0.f;
                }
                #pragma unroll 4
                for (int w = 1; w < 32; w++) {
                    float2 q = Qr[w];
                    float a  = q.x;
                    float nb = -q.y;
                    float2 t5  = Te[w * 10 + 5];
                    float4 t67 = *(const float4*)(Te + w * 10 + 6);
                    float2 t8  = Te[w * 10 + 8];
                    gr[0]=fmaf(t5.x ,a,gr[0]); gi[0]=fmaf(t5.y ,nb,gi[0]);
                    gr[1]=fmaf(t67.x,a,gr[1]); gi[1]=fmaf(t67.y,nb,gi[1]);
                    gr[2]=fmaf(t67.z,a,gr[2]); gi[2]=fmaf(t67.w,nb,gi[2]);
                    gr[3]=fmaf(t8.x ,a,gr[3]); gi[3]=fmaf(t8.y ,nb,gi[3]);
                }
                #pragma unroll
                for (int j = 0; j < 4; j++)
                    Gs[h * NKY + 10 + 2 * j] = make_float2(gr[j], gi[j]);
            } else if (grp == 2) {                // odd ky 1,3,5,7 (j=0..3)
                float gr[4], gi[4];
                #pragma unroll
                for (int j = 0; j < 4; j++) {
                    gr[j] = bd.x - bd.y;
                    gi[j] = (j & 1) ? bd.w : -bd.w;
                }
                #pragma unroll 4
                for (int w = 1; w < 32; w++) {
                    float2 q = Qr[w];
                    float a  = q.x;
                    float nb = -q.y;
                    float4 t01 = *(const float4*)(To + w * 8);
                    float4 t23 = *(const float4*)(To + w * 8 + 2);
                    gr[0]=fmaf(t01.x,a,gr[0]); gi[0]=fmaf(t01.y,nb,gi[0]);
                    gr[1]=fmaf(t01.z,a,gr[1]); gi[1]=fmaf(t01.w,nb,gi[1]);
                    gr[2]=fmaf(t23.x,a,gr[2]); gi[2]=fmaf(t23.y,nb,gi[2]);
                    gr[3]=fmaf(t23.z,a,gr[3]); gi[3]=fmaf(t23.w,nb,gi[3]);
                }
                #pragma unroll
                for (int j = 0; j < 4; j++)
                    Gs[h * NKY + 2 * j + 1] = make_float2(gr[j], gi[j]);
            } else {                              // odd ky 9,11,13,15 (j=4..7)
                float gr[4], gi[4];
                #pragma unroll
                for (int j = 0; j < 4; j++) {
                    int jj = 4 + j;
                    gr[j] = bd.x - bd.y;
                    gi[j] = (jj & 1) ? bd.w : -bd.w;
                }
                #pragma unroll 4
                for (int w = 1; w < 32; w++) {
                    float2 q = Qr[w];
                    float a  = q.x;
                    float nb = -q.y;
                    float4 t45 = *(const float4*)(To + w * 8 + 4);
                    float4 t67 = *(const float4*)(To + w * 8 + 6);
                    gr[0]=fmaf(t45.x,a,gr[0]); gi[0]=fmaf(t45.y,nb,gi[0]);
                    gr[1]=fmaf(t45.z,a,gr[1]); gi[1]=fmaf(t45.w,nb,gi[1]);
                    gr[2]=fmaf(t67.x,a,gr[2]); gi[2]=fmaf(t67.y,nb,gi[2]);
                    gr[3]=fmaf(t67.z,a,gr[3]); gi[3]=fmaf(t67.w,nb,gi[3]);
                }
                #pragma unroll
                for (int j = 0; j < 4; j++)
                    Gs[h * NKY + 9 + 2 * j] = make_float2(gr[j], gi[j]);
            }
        }
    }
    __syncthreads();

    // Phase B: h-DFT, folded, rotation trig.
    if (tid < 17 * NKY) {
        const int a = tid / NKY, ky = tid - a * NKY;
        float cw, sw;
        sincospif((float)a * (1.0f / 64.0f), &sw, &cw);   // e^{i 2pi a/128}

        float2 g0  = Gs[0 * NKY + ky];
        float2 g64 = Gs[64 * NKY + ky];
        const float sgn = (a & 1) ? -1.f : 1.f;
        float C1 = g0.x + sgn * g64.x;
        float C2 = g0.y + sgn * g64.y;
        float S1 = 0.f, S2 = 0.f;

        float tc = cw, ts = sw;
        #pragma unroll 3
        for (int h = 1; h < 64; h++) {
            float2 ga = Gs[h * NKY + ky];
            float2 gb = Gs[(128 - h) * NKY + ky];
            float pr = ga.x + gb.x, pi = ga.y + gb.y;
            float mr = ga.x - gb.x, mi = ga.y - gb.y;
            C1 = fmaf(tc, pr, C1);
            C2 = fmaf(tc, pi, C2);
            S1 = fmaf(ts, mr, S1);
            S2 = fmaf(ts, mi, S2);
            float nc = fmaf(tc, cw, -ts * sw);
            ts = fmaf(tc, sw,  ts * cw);
            tc = nc;
        }

        const float inv = 1.0f / 16384.0f;
        const int b = blockIdx.x >> 7, c = blockIdx.x & 127;
        float2* Xfb = g_Xf + (size_t)c * (NMODE * 8) + b;
        Xfb[(a * NKY + ky) * 8] = make_float2((C1 + S2) * inv, (C2 - S1) * inv);
        if (a >= 1 && a <= 15)
            Xfb[((32 - a) * NKY + ky) * 8] =
                make_float2((C1 - S2) * inv, (C2 + S1) * inv);
    }
}

// ===========================================================================
// Kernel 2 (v4): spectral channel mix with SMEM-tiled Xf.
//   Y[b,c,m] = sum_ct [(re[c,ct,m]-re[ct,c,m]) + i(im[c,ct,m]+im[ct,c,m])] Xf[b,ct,m]
// grid (17 m x 16 c x 2 ct-halves), block 256 = 32 m x 8 c.
// Xf chunk of 16 ct staged to smem transposed [b][ct][m] -> compute reads are
// conflict-free LDS.64; Xf L2 traffic drops 8x (c-tile reuse in smem).
// ===========================================================================
__global__ __launch_bounds__(256) void k_mix(const float* __restrict__ re,
                                             const float* __restrict__ im) {
    __shared__ float2 tile[8][16][33];   // [b][ctl][m], pad 33

    const int mi  = threadIdx.x & 31;
    const int ci  = threadIdx.x >> 5;
    const int m0  = blockIdx.x * 32;
    const int m   = m0 + mi;
    const int c   = blockIdx.y * 8 + ci;
    const int ct0 = blockIdx.z * 64;

    float yr[8], yi[8];
    #pragma unroll
    for (int b = 0; b < 8; b++) { yr[b] = 0.f; yi[b] = 0.f; }

    const float* reA = re + (size_t)c * (128 * NMODE) + m;   // [c][ct][m]
    const float* reB = re + (size_t)c * NMODE + m;           // [ct][c][m]
    const float* imA = im + (size_t)c * (128 * NMODE) + m;
    const float* imB = im + (size_t)c * NMODE + m;

    for (int chunk = 0; chunk < 64; chunk += 16) {
        __syncthreads();
        // stage 16 ct x 32 m x 8 b of Xf (2048 float4), transposing to [b][ct][m]
        const float4* src = (const float4*)g_Xf
                          + ((size_t)(ct0 + chunk) * NMODE + m0) * 4;
        #pragma unroll
        for (int r = 0; r < 8; r++) {
            int i   = threadIdx.x + r * 256;
            int ctl = i >> 7;           // 128 float4 per ct
            int rem = i & 127;
            int mm  = rem >> 2;         // 4 float4 per m
            int bq  = rem & 3;          // float4 bq -> batches 2bq, 2bq+1
            float4 v = src[(size_t)ctl * (NMODE * 4) + mm * 4 + bq];
            tile[2 * bq][ctl][mm]     = make_float2(v.x, v.y);
            tile[2 * bq + 1][ctl][mm] = make_float2(v.z, v.w);
        }
        __syncthreads();

        #pragma unroll 4
        for (int ctl = 0; ctl < 16; ctl++) {
            int ct = ct0 + chunk + ctl;
            float wre = reA[ct * NMODE] - reB[(size_t)ct * (128 * NMODE)];
            float wim = imA[ct * NMODE] + imB[(size_t)ct * (128 * NMODE)];
            #pragma unroll
            for (int b = 0; b < 8; b++) {
                float2 x = tile[b][ctl][mi];
                yr[b] = fmaf(wre, x.x, fmaf(-wim, x.y, yr[b]));
                yi[b] = fmaf(wre, x.y, fmaf( wim, x.x, yi[b]));
            }
        }
    }
    float2* outY = blockIdx.z ? g_Y2 : g_Y;
    #pragma unroll
    for (int b = 0; b < 8; b++)
        outY[(size_t)(b * 128 + c) * NMODE + m] = make_float2(yr[b], yi[b]);
}

// ===========================================================================
// Fused inverse per (b,c) slice. 320 threads, forced 4 blocks/SM.
// Phase A (kx->h, folded, rotation trig): P/M built from g_Y + g_Y2;
//   Z[h]=(C1-S2, C2+S1), Z[128-h]=(C1+S2, C2-S1)  -> Zev/Zod (ky parity-split)
// Phase B (ky->w c2r, QUARTER-folded, 256 threads): thread (h, w<=31) emits
//   out[w], out[128-w], out[64-w], out[64+w]; w=0 thread also emits 32/96.
// ===========================================================================
__global__ __launch_bounds__(320, 4) void k_inv(float* __restrict__ out) {
    __shared__ float2 tb[128];
    __shared__ float2 Pa[17 * NKY];
    __shared__ float2 Ma[17 * NKY];
    __shared__ float2 Zev[128][10];     // even ky j=0..8 (pad 10 -> 80B rows)
    __shared__ float2 Zod[128][8];      // odd  ky j=0..7

    const int tid = threadIdx.x;
    if (tid < 128) {
        float s, c;
        sincospif((float)tid * (2.0f / 128.0f), &s, &c);
        tb[tid] = make_float2(c, s);
    }

    const float2* Yp  = g_Y  + (size_t)blockIdx.x * NMODE;
    const float2* Yp2 = g_Y2 + (size_t)blockIdx.x * NMODE;
    if (tid < 17 * NKY) {
        int a = tid / NKY, ky = tid - a * NKY;
        float2 ya = Yp[a * NKY + ky], yb = Yp2[a * NKY + ky];
        float2 yp = make_float2(ya.x + yb.x, ya.y + yb.y);
        float2 P, M;
        if (a == 0)       { P = yp; M = make_float2(0.f, 0.f); }
        else if (a == 16) { P = yp; M = yp; }
        else {
            float2 na = Yp[(32 - a) * NKY + ky], nb = Yp2[(32 - a) * NKY + ky];
            float2 yn = make_float2(na.x + nb.x, na.y + nb.y);
            P = make_float2(yp.x + yn.x, yp.y + yn.y);
            M = make_float2(yp.x - yn.x, yp.y - yn.y);
        }
        Pa[tid] = P;
        Ma[tid] = M;
    }
    __syncthreads();

    // Phase A
    if (tid < 272) {
        const int ky = tid % NKY;
        const int hb = tid / NKY;           // 0..15
        const int kj = ky >> 1;
        const bool odd = (ky & 1);
        float cw[4], sw[4], tc[4], ts[4];
        float C1[4], C2[4], S1[4], S2[4];
        #pragma unroll
        for (int j = 0; j < 4; j++) {
            int h = hb + 16 * j;
            sincospif((float)h * (1.0f / 64.0f), &sw[j], &cw[j]);
            tc[j] = 1.f; ts[j] = 0.f;
            C1[j] = 0.f; C2[j] = 0.f; S1[j] = 0.f; S2[j] = 0.f;
        }
        #pragma unroll
        for (int a = 0; a < NKY; a++) {
            float2 P = Pa[a * NKY + ky];
            float2 M = Ma[a * NKY + ky];
            #pragma unroll
            for (int j = 0; j < 4; j++) {
                C1[j] = fmaf(tc[j], P.x, C1[j]);
                C2[j] = fmaf(tc[j], P.y, C2[j]);
                S1[j] = fmaf(ts[j], M.x, S1[j]);
                S2[j] = fmaf(ts[j], M.y, S2[j]);
                float nc = fmaf(tc[j], cw[j], -ts[j] * sw[j]);
                ts[j] = fmaf(tc[j], sw[j],  ts[j] * cw[j]);
                tc[j] = nc;
            }
        }
        #pragma unroll
        for (int j = 0; j < 4; j++) {
            int h = hb + 16 * j;
            float2 zf = make_float2(C1[j] - S2[j], C2[j] + S1[j]);
            float2 zm = make_float2(C1[j] + S2[j], C2[j] - S1[j]);
            if (odd) {
                Zod[h][kj] = zf;
                if (h >= 1) Zod[128 - h][kj] = zm;
            } else {
                Zev[h][kj] = zf;
                if (h >= 1) Zev[128 - h][kj] = zm;
            }
        }
    } else if (tid < 289) {
        const int ky = tid - 272;           // h = 64: cos(pi a)=(-1)^a, sin=0
        float C1 = 0.f, C2 = 0.f;
        #pragma unroll
        for (int a = 0; a < NKY; a++) {
            float2 P = Pa[a * NKY + ky];
            float sg = (a & 1) ? -1.f : 1.f;
            C1 = fmaf(sg, P.x, C1);
            C2 = fmaf(sg, P.y, C2);
        }
        if (ky & 1) Zod[64][ky >> 1] = make_float2(C1, C2);
        else        Zev[64][ky >> 1] = make_float2(C1, C2);
    }
    __syncthreads();

    // Phase B
    if (tid < 256) {
        const int w  = tid & 31;
        const int h0 = (tid >> 5) * 16;
        float ck[NKY], sk[NKY];
        #pragma unroll
        for (int ky = 0; ky < NKY; ky++) {
            float2 t = tb[(ky * w) & 127];
            float a = ky ? 2.0f : 1.0f;
            ck[ky] = a * t.x;
            sk[ky] = a * t.y;
        }

        float* op = out + (size_t)blockIdx.x * 16384;
        for (int h = h0; h < h0 + 16; h++) {
            float4 e01 = *(const float4*)&Zev[h][0];
            float4 e23 = *(const float4*)&Zev[h][2];
            float4 e45 = *(const float4*)&Zev[h][4];
            float4 e67 = *(const float4*)&Zev[h][6];
            float2 e8  = Zev[h][8];
            float4 o01 = *(const float4*)&Zod[h][0];
            float4 o23 = *(const float4*)&Zod[h][2];
            float4 o45 = *(const float4*)&Zod[h][4];
            float4 o67 = *(const float4*)&Zod[h][6];

            float Ce = ck[0] * e01.x;          float Se = sk[0] * e01.y;
            Ce = fmaf(ck[2],  e01.z, Ce);      Se = fmaf(sk[2],  e01.w, Se);
            Ce = fmaf(ck[4],  e23.x, Ce);      Se = fmaf(sk[4],  e23.y, Se);
            Ce = fmaf(ck[6],  e23.z, Ce);      Se = fmaf(sk[6],  e23.w, Se);
            Ce = fmaf(ck[8],  e45.x, Ce);      Se = fmaf(sk[8],  e45.y, Se);
            Ce = fmaf(ck[10], e45.z, Ce);      Se = fmaf(sk[10], e45.w, Se);
            Ce = fmaf(ck[12], e67.x, Ce);      Se = fmaf(sk[12], e67.y, Se);
            Ce = fmaf(ck[14], e67.z, Ce);      Se = fmaf(sk[14], e67.w, Se);
            Ce = fmaf(ck[16], e8.x,  Ce);      Se = fmaf(sk[16], e8.y,  Se);

            float Co = ck[1] * o01.x;          float So = sk[1] * o01.y;
            Co = fmaf(ck[3],  o01.z, Co);      So = fmaf(sk[3],  o01.w, So);
            Co = fmaf(ck[5],  o23.x, Co);      So = fmaf(sk[5],  o23.y, So);
            Co = fmaf(ck[7],  o23.z, Co);      So = fmaf(sk[7],  o23.w, So);
            Co = fmaf(ck[9],  o45.x, Co);      So = fmaf(sk[9],  o45.y, So);
            Co = fmaf(ck[11], o45.z, Co);      So = fmaf(sk[11], o45.w, So);
            Co = fmaf(ck[13], o67.x, Co);      So = fmaf(sk[13], o67.y, So);
            Co = fmaf(ck[15], o67.z, Co);      So = fmaf(sk[15], o67.w, So);

            float Cp = Ce + Co, Cm = Ce - Co;
            float Sp = Se + So, Sm = Se - So;
            float* oph = op + h * 128;
            oph[w] = Cp - Sp;
            if (w) {
                oph[128 - w] = Cp + Sp;
                oph[64 - w]  = Cm + Sm;
                oph[64 + w]  = Cm - Sm;
            } else {
                oph[64] = Cm;
                // w = 32 / 96 (self-paired under w<->64-w):
                float C32 = e01.x;
                C32 = fmaf(-2.f, e01.z, C32);
                C32 = fmaf( 2.f, e23.x, C32);
                C32 = fmaf(-2.f, e23.z, C32);
                C32 = fmaf( 2.f, e45.x, C32);
                C32 = fmaf(-2.f, e45.z, C32);
                C32 = fmaf( 2.f, e67.x, C32);
                C32 = fmaf(-2.f, e67.z, C32);
                C32 = fmaf( 2.f, e8.x,  C32);
                float S32 = o01.y - o01.w + o23.y - o23.w
                          + o45.y - o45.w + o67.y - o67.w;
                S32 *= 2.f;
                oph[32] = C32 - S32;
                oph[96] = C32 + S32;
            }
        }
    }
}

extern "C" void kernel_launch(void* const* d_in, const int* in_sizes, int n_in,
                              void* d_out, int out_size) {
    const float* X  = (const float*)d_in[0];
    const float* re = (const float*)d_in[1];
    const float* im = (const float*)d_in[2];
    float* out = (float*)d_out;

    const int smem_fwd = 64 * 16 + (32 * 10 + 32 * 8 + 128 * NKY) * 8
                       + 2 * (64 * 33) * 8;   // 56832 B
    cudaFuncSetAttribute(k_fwd, cudaFuncAttributeMaxDynamicSharedMemorySize, smem_fwd);

    k_fwd<<<NSLICE, 320, smem_fwd>>>(X);
    k_mix<<<dim3(17, 16, 2), 256>>>(re, im);
    k_inv<<<NSLICE, 320>>>(out);
}

// round 16
// speedup vs baseline: 1.1226x; 1.1226x over previous
#include <cuda_runtime.h>

// OrbitalSpectralConv: B=8, C=128, H=W=128; kept modes: 32 kx rows x 17 ky cols.
// kx rows: mk 0..16 -> kx = mk; mk 17..31 -> kx = mk+96 == -(32-mk) mod 128.
#define NKY   17
#define NMODE 544           // 32*17
#define NSLICE 1024         // B*C

// Scratch (allocation banned -> device globals).
__device__ float2 g_Xf[128 * NMODE * 8];         // 4.45 MB  [ct][m][b]
__device__ float2 g_Y [NSLICE * NMODE];          // 4.45 MB  [b][c][m]  (ct 0..63)
__device__ float2 g_Y2[NSLICE * NMODE];          // 4.45 MB  [b][c][m]  (ct 64..127)

// ===========================================================================
// Fused forward per (b,c) slice. 320 threads, 56832 B dynamic smem,
// forced 4 blocks/SM (measured win in R15: 50.4 -> 45.2 us).
// Phase A (w-DFT, DOUBLE-folded, 256 threads = 64 h x 4 ky-groups):
//   even ky=2j: re = Sp0+Sp64+(-1)^j Sp32 + sum_{w=1..31} Ae[w] cos; im = -sum Be sin
//   odd  ky=2j+1: re = Sp0-Sp64 + sum Ao cos; im = -(-1)^j Sm32 - sum Bo sin
//   QE[h][w]=(Ae,Be), QO[h][w]=(Ao,Bo); Ae/Ao = Sp[w]+/-Sp[64-w];
//   Be/Bo = Sm[w]-/+Sm[64-w]; Sp[w]=x[w]+x[128-w], Sm[w]=x[w]-x[128-w].
// Phase B (h-DFT, folded, rotation trig, 289 threads = (a,ky)):
//   Xf[+a]=(C1+S2, C2-S1), Xf[-a]=(C1-S2, C2+S1), scaled 1/16384 -> g_Xf[c][m][b]
// ===========================================================================
__global__ __launch_bounds__(320, 4) void k_fwd(const float* __restrict__ X) {
    extern __shared__ char smraw[];
    float4* Bd = (float4*)smraw;                 // [64]   (Sp0, Sp64, Sp32, Sm32)
    float2* Te = (float2*)(Bd + 64);             // [32][10] cos/sin(2pi*2j*w/128)
    float2* To = Te + 32 * 10;                   // [32][8]  cos/sin(2pi*(2j+1)*w/128)
    float2* Gs = To + 32 * 8;                    // [128][17]
    float2* QE = Gs + 128 * NKY;                 // [64][33]  (Ae, Be)
    float2* QO = QE + 64 * 33;                   // [64][33]  (Ao, Bo)

    const int tid = threadIdx.x;

    if (tid < 320) {
        int w = tid / 10, j = tid - (tid / 10) * 10;
        float s, c;
        sincospif((float)((w * 2 * j) & 127) * (2.0f / 128.0f), &s, &c);
        Te[tid] = make_float2(c, s);
    }
    if (tid < 256) {
        int w = tid >> 3, j = tid & 7;
        float s, c;
        sincospif((float)((w * (2 * j + 1)) & 127) * (2.0f / 128.0f), &s, &c);
        To[tid] = make_float2(c, s);
    }

    const float* Xp = X + (size_t)blockIdx.x * 16384;

    const int hl  = tid & 63;
    const int grp = tid >> 6;

    for (int half = 0; half < 2; half++) {
        __syncthreads();    // covers trig init (1st) and QE/QO/Bd reuse (2nd)
        for (int i = tid; i < 2048; i += 320) {
            int hr = i >> 5, w = i & 31;
            const float* row = Xp + (half * 64 + hr) * 128;
            if (w == 0) {
                float x0 = row[0], x64 = row[64], x32 = row[32], x96 = row[96];
                Bd[hr] = make_float4(x0, x64, x32 + x96, x32 - x96);
            } else {
                float xa = row[w], xb = row[64 - w], xc = row[64 + w], xd = row[128 - w];
                float sp  = xa + xd, sm  = xa - xd;
                float spb = xb + xc, smb = xb - xc;
                QE[hr * 33 + w] = make_float2(sp + spb, sm - smb);
                QO[hr * 33 + w] = make_float2(sp - spb, sm + smb);
            }
        }
        __syncthreads();

        if (grp < 4) {
            const float4 bd = Bd[hl];
            const int h = half * 64 + hl;
            const float2* Qr = (grp < 2 ? QE : QO) + hl * 33;

            if (grp == 0) {                       // even ky 0,2,4,6,8
                float gr[5], gi[5];
                #pragma unroll
                for (int j = 0; j < 5; j++) {
                    gr[j] = bd.x + bd.y + ((j & 1) ? -bd.z : bd.z);
                    gi[j] = 0.f;
                }
                #pragma unroll 4
                for (int w = 1; w < 32; w++) {
                    float2 q = Qr[w];
                    float a  = q.x;
                    float nb = -q.y;
                    float4 t01 = *(const float4*)(Te + w * 10);
                    float4 t23 = *(const float4*)(Te + w * 10 + 2);
                    float2 t4  = Te[w * 10 + 4];
                    gr[0]=fmaf(t01.x,a,gr[0]); gi[0]=fmaf(t01.y,nb,gi[0]);
                    gr[1]=fmaf(t01.z,a,gr[1]); gi[1]=fmaf(t01.w,nb,gi[1]);
                    gr[2]=fmaf(t23.x,a,gr[2]); gi[2]=fmaf(t23.y,nb,gi[2]);
                    gr[3]=fmaf(t23.z,a,gr[3]); gi[3]=fmaf(t23.w,nb,gi[3]);
                    gr[4]=fmaf(t4.x ,a,gr[4]); gi[4]=fmaf(t4.y ,nb,gi[4]);
                }
                #pragma unroll
                for (int j = 0; j < 5; j++)
                    Gs[h * NKY + 2 * j] = make_float2(gr[j], gi[j]);
            } else if (grp == 1) {                // even ky 10,12,14,16 (j=5..8)
                float gr[4], gi[4];
                #pragma unroll
                for (int j = 0; j < 4; j++) {
                    int jj = 5 + j;
                    gr[j] = bd.x + bd.y + ((jj & 1) ? -bd.z : bd.z);
                    gi[j] = 0.f;
                }
                #pragma unroll 4
                for (int w = 1; w < 32; w++) {
                    float2 q = Qr[w];
                    float a  = q.x;
                    float nb = -q.y;
                    float2 t5  = Te[w * 10 + 5];
                    float4 t67 = *(const float4*)(Te + w * 10 + 6);
                    float2 t8  = Te[w * 10 + 8];
                    gr[0]=fmaf(t5.x ,a,gr[0]); gi[0]=fmaf(t5.y ,nb,gi[0]);
                    gr[1]=fmaf(t67.x,a,gr[1]); gi[1]=fmaf(t67.y,nb,gi[1]);
                    gr[2]=fmaf(t67.z,a,gr[2]); gi[2]=fmaf(t67.w,nb,gi[2]);
                    gr[3]=fmaf(t8.x ,a,gr[3]); gi[3]=fmaf(t8.y ,nb,gi[3]);
                }
                #pragma unroll
                for (int j = 0; j < 4; j++)
                    Gs[h * NKY + 10 + 2 * j] = make_float2(gr[j], gi[j]);
            } else if (grp == 2) {                // odd ky 1,3,5,7 (j=0..3)
                float gr[4], gi[4];
                #pragma unroll
                for (int j = 0; j < 4; j++) {
                    gr[j] = bd.x - bd.y;
                    gi[j] = (j & 1) ? bd.w : -bd.w;
                }
                #pragma unroll 4
                for (int w = 1; w < 32; w++) {
                    float2 q = Qr[w];
                    float a  = q.x;
                    float nb = -q.y;
                    float4 t01 = *(const float4*)(To + w * 8);
                    float4 t23 = *(const float4*)(To + w * 8 + 2);
                    gr[0]=fmaf(t01.x,a,gr[0]); gi[0]=fmaf(t01.y,nb,gi[0]);
                    gr[1]=fmaf(t01.z,a,gr[1]); gi[1]=fmaf(t01.w,nb,gi[1]);
                    gr[2]=fmaf(t23.x,a,gr[2]); gi[2]=fmaf(t23.y,nb,gi[2]);
                    gr[3]=fmaf(t23.z,a,gr[3]); gi[3]=fmaf(t23.w,nb,gi[3]);
                }
                #pragma unroll
                for (int j = 0; j < 4; j++)
                    Gs[h * NKY + 2 * j + 1] = make_float2(gr[j], gi[j]);
            } else {                              // odd ky 9,11,13,15 (j=4..7)
                float gr[4], gi[4];
                #pragma unroll
                for (int j = 0; j < 4; j++) {
                    int jj = 4 + j;
                    gr[j] = bd.x - bd.y;
                    gi[j] = (jj & 1) ? bd.w : -bd.w;
                }
                #pragma unroll 4
                for (int w = 1; w < 32; w++) {
                    float2 q = Qr[w];
                    float a  = q.x;
                    float nb = -q.y;
                    float4 t45 = *(const float4*)(To + w * 8 + 4);
                    float4 t67 = *(const float4*)(To + w * 8 + 6);
                    gr[0]=fmaf(t45.x,a,gr[0]); gi[0]=fmaf(t45.y,nb,gi[0]);
                    gr[1]=fmaf(t45.z,a,gr[1]); gi[1]=fmaf(t45.w,nb,gi[1]);
                    gr[2]=fmaf(t67.x,a,gr[2]); gi[2]=fmaf(t67.y,nb,gi[2]);
                    gr[3]=fmaf(t67.z,a,gr[3]); gi[3]=fmaf(t67.w,nb,gi[3]);
                }
                #pragma unroll
                for (int j = 0; j < 4; j++)
                    Gs[h * NKY + 9 + 2 * j] = make_float2(gr[j], gi[j]);
            }
        }
    }
    __syncthreads();

    // Phase B: h-DFT, folded, rotation trig.
    if (tid < 17 * NKY) {
        const int a = tid / NKY, ky = tid - a * NKY;
        float cw, sw;
        sincospif((float)a * (1.0f / 64.0f), &sw, &cw);   // e^{i 2pi a/128}

        float2 g0  = Gs[0 * NKY + ky];
        float2 g64 = Gs[64 * NKY + ky];
        const float sgn = (a & 1) ? -1.f : 1.f;
        float C1 = g0.x + sgn * g64.x;
        float C2 = g0.y + sgn * g64.y;
        float S1 = 0.f, S2 = 0.f;

        float tc = cw, ts = sw;
        #pragma unroll 3
        for (int h = 1; h < 64; h++) {
            float2 ga = Gs[h * NKY + ky];
            float2 gb = Gs[(128 - h) * NKY + ky];
            float pr = ga.x + gb.x, pi = ga.y + gb.y;
            float mr = ga.x - gb.x, mi = ga.y - gb.y;
            C1 = fmaf(tc, pr, C1);
            C2 = fmaf(tc, pi, C2);
            S1 = fmaf(ts, mr, S1);
            S2 = fmaf(ts, mi, S2);
            float nc = fmaf(tc, cw, -ts * sw);
            ts = fmaf(tc, sw,  ts * cw);
            tc = nc;
        }

        const float inv = 1.0f / 16384.0f;
        const int b = blockIdx.x >> 7, c = blockIdx.x & 127;
        float2* Xfb = g_Xf + (size_t)c * (NMODE * 8) + b;
        Xfb[(a * NKY + ky) * 8] = make_float2((C1 + S2) * inv, (C2 - S1) * inv);
        if (a >= 1 && a <= 15)
            Xfb[((32 - a) * NKY + ky) * 8] =
                make_float2((C1 - S2) * inv, (C2 + S1) * inv);
    }
}

// ===========================================================================
// Kernel 2 (v4): spectral channel mix with SMEM-tiled Xf.
//   Y[b,c,m] = sum_ct [(re[c,ct,m]-re[ct,c,m]) + i(im[c,ct,m]+im[ct,c,m])] Xf[b,ct,m]
// grid (17 m x 16 c x 2 ct-halves), block 256 = 32 m x 8 c.
// Xf chunk of 16 ct staged to smem transposed [b][ct][m] -> compute reads are
// conflict-free LDS.64; Xf L2 traffic drops 8x (c-tile reuse in smem).
// ===========================================================================
__global__ __launch_bounds__(256) void k_mix(const float* __restrict__ re,
                                             const float* __restrict__ im) {
    __shared__ float2 tile[8][16][33];   // [b][ctl][m], pad 33

    const int mi  = threadIdx.x & 31;
    const int ci  = threadIdx.x >> 5;
    const int m0  = blockIdx.x * 32;
    const int m   = m0 + mi;
    const int c   = blockIdx.y * 8 + ci;
    const int ct0 = blockIdx.z * 64;

    float yr[8], yi[8];
    #pragma unroll
    for (int b = 0; b < 8; b++) { yr[b] = 0.f; yi[b] = 0.f; }

    const float* reA = re + (size_t)c * (128 * NMODE) + m;   // [c][ct][m]
    const float* reB = re + (size_t)c * NMODE + m;           // [ct][c][m]
    const float* imA = im + (size_t)c * (128 * NMODE) + m;
    const float* imB = im + (size_t)c * NMODE + m;

    for (int chunk = 0; chunk < 64; chunk += 16) {
        __syncthreads();
        // stage 16 ct x 32 m x 8 b of Xf (2048 float4), transposing to [b][ct][m]
        const float4* src = (const float4*)g_Xf
                          + ((size_t)(ct0 + chunk) * NMODE + m0) * 4;
        #pragma unroll
        for (int r = 0; r < 8; r++) {
            int i   = threadIdx.x + r * 256;
            int ctl = i >> 7;           // 128 float4 per ct
            int rem = i & 127;
            int mm  = rem >> 2;         // 4 float4 per m
            int bq  = rem & 3;          // float4 bq -> batches 2bq, 2bq+1
            float4 v = src[(size_t)ctl * (NMODE * 4) + mm * 4 + bq];
            tile[2 * bq][ctl][mm]     = make_float2(v.x, v.y);
            tile[2 * bq + 1][ctl][mm] = make_float2(v.z, v.w);
        }
        __syncthreads();

        #pragma unroll 4
        for (int ctl = 0; ctl < 16; ctl++) {
            int ct = ct0 + chunk + ctl;
            float wre = reA[ct * NMODE] - reB[(size_t)ct * (128 * NMODE)];
            float wim = imA[ct * NMODE] + imB[(size_t)ct * (128 * NMODE)];
            #pragma unroll
            for (int b = 0; b < 8; b++) {
                float2 x = tile[b][ctl][mi];
                yr[b] = fmaf(wre, x.x, fmaf(-wim, x.y, yr[b]));
                yi[b] = fmaf(wre, x.y, fmaf( wim, x.x, yi[b]));
            }
        }
    }
    float2* outY = blockIdx.z ? g_Y2 : g_Y;
    #pragma unroll
    for (int b = 0; b < 8; b++)
        outY[(size_t)(b * 128 + c) * NMODE + m] = make_float2(yr[b], yi[b]);
}

// ===========================================================================
// Fused inverse per (b,c) slice. 320 threads, NO min-blocks bound (R15's
// (320,4) forced regs 56->48 and spilled the rotation chains: -15 us).
// Phase A (kx->h, folded, rotation trig): P/M built from g_Y + g_Y2;
//   Z[h]=(C1-S2, C2+S1), Z[128-h]=(C1+S2, C2-S1)  -> Zev/Zod (ky parity-split)
// Phase B (ky->w c2r, QUARTER-folded, 256 threads): thread (h, w<=31) emits
//   out[w], out[128-w], out[64-w], out[64+w]; w=0 thread also emits 32/96.
// ===========================================================================
__global__ __launch_bounds__(320) void k_inv(float* __restrict__ out) {
    __shared__ float2 tb[128];
    __shared__ float2 Pa[17 * NKY];
    __shared__ float2 Ma[17 * NKY];
    __shared__ float2 Zev[128][10];     // even ky j=0..8 (pad 10 -> 80B rows)
    __shared__ float2 Zod[128][8];      // odd  ky j=0..7

    const int tid = threadIdx.x;
    if (tid < 128) {
        float s, c;
        sincospif((float)tid * (2.0f / 128.0f), &s, &c);
        tb[tid] = make_float2(c, s);
    }

    const float2* Yp  = g_Y  + (size_t)blockIdx.x * NMODE;
    const float2* Yp2 = g_Y2 + (size_t)blockIdx.x * NMODE;
    if (tid < 17 * NKY) {
        int a = tid / NKY, ky = tid - a * NKY;
        float2 ya = Yp[a * NKY + ky], yb = Yp2[a * NKY + ky];
        float2 yp = make_float2(ya.x + yb.x, ya.y + yb.y);
        float2 P, M;
        if (a == 0)       { P = yp; M = make_float2(0.f, 0.f); }
        else if (a == 16) { P = yp; M = yp; }
        else {
            float2 na = Yp[(32 - a) * NKY + ky], nb = Yp2[(32 - a) * NKY + ky];
            float2 yn = make_float2(na.x + nb.x, na.y + nb.y);
            P = make_float2(yp.x + yn.x, yp.y + yn.y);
            M = make_float2(yp.x - yn.x, yp.y - yn.y);
        }
        Pa[tid] = P;
        Ma[tid] = M;
    }
    __syncthreads();

    // Phase A
    if (tid < 272) {
        const int ky = tid % NKY;
        const int hb = tid / NKY;           // 0..15
        const int kj = ky >> 1;
        const bool odd = (ky & 1);
        float cw[4], sw[4], tc[4], ts[4];
        float C1[4], C2[4], S1[4], S2[4];
        #pragma unroll
        for (int j = 0; j < 4; j++) {
            int h = hb + 16 * j;
            sincospif((float)h * (1.0f / 64.0f), &sw[j], &cw[j]);
            tc[j] = 1.f; ts[j] = 0.f;
            C1[j] = 0.f; C2[j] = 0.f; S1[j] = 0.f; S2[j] = 0.f;
        }
        #pragma unroll
        for (int a = 0; a < NKY; a++) {
            float2 P = Pa[a * NKY + ky];
            float2 M = Ma[a * NKY + ky];
            #pragma unroll
            for (int j = 0; j < 4; j++) {
                C1[j] = fmaf(tc[j], P.x, C1[j]);
                C2[j] = fmaf(tc[j], P.y, C2[j]);
                S1[j] = fmaf(ts[j], M.x, S1[j]);
                S2[j] = fmaf(ts[j], M.y, S2[j]);
                float nc = fmaf(tc[j], cw[j], -ts[j] * sw[j]);
                ts[j] = fmaf(tc[j], sw[j],  ts[j] * cw[j]);
                tc[j] = nc;
            }
        }
        #pragma unroll
        for (int j = 0; j < 4; j++) {
            int h = hb + 16 * j;
            float2 zf = make_float2(C1[j] - S2[j], C2[j] + S1[j]);
            float2 zm = make_float2(C1[j] + S2[j], C2[j] - S1[j]);
            if (odd) {
                Zod[h][kj] = zf;
                if (h >= 1) Zod[128 - h][kj] = zm;
            } else {
                Zev[h][kj] = zf;
                if (h >= 1) Zev[128 - h][kj] = zm;
            }
        }
    } else if (tid < 289) {
        const int ky = tid - 272;           // h = 64: cos(pi a)=(-1)^a, sin=0
        float C1 = 0.f, C2 = 0.f;
        #pragma unroll
        for (int a = 0; a < NKY; a++) {
            float2 P = Pa[a * NKY + ky];
            float sg = (a & 1) ? -1.f : 1.f;
            C1 = fmaf(sg, P.x, C1);
            C2 = fmaf(sg, P.y, C2);
        }
        if (ky & 1) Zod[64][ky >> 1] = make_float2(C1, C2);
        else        Zev[64][ky >> 1] = make_float2(C1, C2);
    }
    __syncthreads();

    // Phase B
    if (tid < 256) {
        const int w  = tid & 31;
        const int h0 = (tid >> 5) * 16;
        float ck[NKY], sk[NKY];
        #pragma unroll
        for (int ky = 0; ky < NKY; ky++) {
            float2 t = tb[(ky * w) & 127];
            float a = ky ? 2.0f : 1.0f;
            ck[ky] = a * t.x;
            sk[ky] = a * t.y;
        }

        float* op = out + (size_t)blockIdx.x * 16384;
        for (int h = h0; h < h0 + 16; h++) {
            float4 e01 = *(const float4*)&Zev[h][0];
            float4 e23 = *(const float4*)&Zev[h][2];
            float4 e45 = *(const float4*)&Zev[h][4];
            float4 e67 = *(const float4*)&Zev[h][6];
            float2 e8  = Zev[h][8];
            float4 o01 = *(const float4*)&Zod[h][0];
            float4 o23 = *(const float4*)&Zod[h][2];
            float4 o45 = *(const float4*)&Zod[h][4];
            float4 o67 = *(const float4*)&Zod[h][6];

            float Ce = ck[0] * e01.x;          float Se = sk[0] * e01.y;
            Ce = fmaf(ck[2],  e01.z, Ce);      Se = fmaf(sk[2],  e01.w, Se);
            Ce = fmaf(ck[4],  e23.x, Ce);      Se = fmaf(sk[4],  e23.y, Se);
            Ce = fmaf(ck[6],  e23.z, Ce);      Se = fmaf(sk[6],  e23.w, Se);
            Ce = fmaf(ck[8],  e45.x, Ce);      Se = fmaf(sk[8],  e45.y, Se);
            Ce = fmaf(ck[10], e45.z, Ce);      Se = fmaf(sk[10], e45.w, Se);
            Ce = fmaf(ck[12], e67.x, Ce);      Se = fmaf(sk[12], e67.y, Se);
            Ce = fmaf(ck[14], e67.z, Ce);      Se = fmaf(sk[14], e67.w, Se);
            Ce = fmaf(ck[16], e8.x,  Ce);      Se = fmaf(sk[16], e8.y,  Se);

            float Co = ck[1] * o01.x;          float So = sk[1] * o01.y;
            Co = fmaf(ck[3],  o01.z, Co);      So = fmaf(sk[3],  o01.w, So);
            Co = fmaf(ck[5],  o23.x, Co);      So = fmaf(sk[5],  o23.y, So);
            Co = fmaf(ck[7],  o23.z, Co);      So = fmaf(sk[7],  o23.w, So);
            Co = fmaf(ck[9],  o45.x, Co);      So = fmaf(sk[9],  o45.y, So);
            Co = fmaf(ck[11], o45.z, Co);      So = fmaf(sk[11], o45.w, So);
            Co = fmaf(ck[13], o67.x, Co);      So = fmaf(sk[13], o67.y, So);
            Co = fmaf(ck[15], o67.z, Co);      So = fmaf(sk[15], o67.w, So);

            float Cp = Ce + Co, Cm = Ce - Co;
            float Sp = Se + So, Sm = Se - So;
            float* oph = op + h * 128;
            oph[w] = Cp - Sp;
            if (w) {
                oph[128 - w] = Cp + Sp;
                oph[64 - w]  = Cm + Sm;
                oph[64 + w]  = Cm - Sm;
            } else {
                oph[64] = Cm;
                // w = 32 / 96 (self-paired under w<->64-w):
                float C32 = e01.x;
                C32 = fmaf(-2.f, e01.z, C32);
                C32 = fmaf( 2.f, e23.x, C32);
                C32 = fmaf(-2.f, e23.z, C32);
                C32 = fmaf( 2.f, e45.x, C32);
                C32 = fmaf(-2.f, e45.z, C32);
                C32 = fmaf( 2.f, e67.x, C32);
                C32 = fmaf(-2.f, e67.z, C32);
                C32 = fmaf( 2.f, e8.x,  C32);
                float S32 = o01.y - o01.w + o23.y - o23.w
                          + o45.y - o45.w + o67.y - o67.w;
                S32 *= 2.f;
                oph[32] = C32 - S32;
                oph[96] = C32 + S32;
            }
        }
    }
}

extern "C" void kernel_launch(void* const* d_in, const int* in_sizes, int n_in,
                              void* d_out, int out_size) {
    const float* X  = (const float*)d_in[0];
    const float* re = (const float*)d_in[1];
    const float* im = (const float*)d_in[2];
    float* out = (float*)d_out;

    const int smem_fwd = 64 * 16 + (32 * 10 + 32 * 8 + 128 * NKY) * 8
                       + 2 * (64 * 33) * 8;   // 56832 B
    cudaFuncSetAttribute(k_fwd, cudaFuncAttributeMaxDynamicSharedMemorySize, smem_fwd);

    k_fwd<<<NSLICE, 320, smem_fwd>>>(X);
    k_mix<<<dim3(17, 16, 2), 256>>>(re, im);
    k_inv<<<NSLICE, 320>>>(out);
}